// round 16
// baseline (speedup 1.0000x reference)
#include <cuda_runtime.h>

// Linear-chain CRF NLL: fused forward (log-partition) + gold score.
// B=4096, L=1024, T=32. ONE batch per 32-thread warp-block -> 4096 warps.
// bf16 state exchange: fv kept renormalized (max ~1) and stored in SMEM as
// bf16; lane l = r + 8c reads its 8-prev chunk with ONE LDS.128 (16 B),
// expands bf16->f32 with shifts/masks (bf16 = top half of f32), packs
// even/odd prev pairs as f32x2, runs 16 fma2 over 4 row-slots
// (rows r + 8*(c^s)), reduce-scatters with shfl_xor 16/8, folds, applies
// exp(feat). Exact power-of-2 renorm every 4 steps. Emission gold fused
// in-loop; transition gold in a bulk phase. 2-buffer feat prefetch.

namespace {

constexpr int T_ = 32;
constexpr int L_ = 1024;
constexpr int START_ = 30;
constexpr int STOP_ = 31;
constexpr unsigned FULL_ = 0xffffffffu;
typedef unsigned long long u64;

__device__ __forceinline__ u64 pack2(float lo, float hi) {
    u64 r;
    asm("mov.b64 %0, {%1, %2};" : "=l"(r) : "f"(lo), "f"(hi));
    return r;
}
__device__ __forceinline__ void unpack2(u64 v, float& lo, float& hi) {
    asm("mov.b64 {%0, %1}, %2;" : "=f"(lo), "=f"(hi) : "l"(v));
}
__device__ __forceinline__ void fma2(u64& acc, u64 a, u64 b) {
    asm("fma.rn.f32x2 %0, %1, %2, %0;" : "+l"(acc) : "l"(a), "l"(b));
}
__device__ __forceinline__ u64 add2(u64 a, u64 b) {
    u64 r;
    asm("add.rn.f32x2 %0, %1, %2;" : "=l"(r) : "l"(a), "l"(b));
    return r;
}
// bf16x2 word {lo16=bf(even), hi16=bf(odd)} -> f32x2 {even, odd}.
__device__ __forceinline__ u64 bf2f2(unsigned w) {
    const float fe = __uint_as_float(w << 16);
    const float fo = __uint_as_float(w & 0xffff0000u);
    return pack2(fe, fo);
}
__device__ __forceinline__ unsigned short f2bf(float f) {
    unsigned short h;
    asm("cvt.rn.bf16.f32 %0, %1;" : "=h"(h) : "f"(f));
    return h;
}

template <int TS>
__device__ __forceinline__ void crf_body(const float* __restrict__ feats,
                                         const float* __restrict__ trans,
                                         const unsigned* __restrict__ tagw,
                                         float* __restrict__ out,
                                         unsigned short (*sv)[32]) {
    const int t = threadIdx.x;
    const int r = t & 7;
    const int c = t >> 3;
    const int b = blockIdx.x;

    // E2[s][m] = {exp(trans[row_s][8c+2m]), exp(trans[row_s][8c+2m+1])},
    // row_s = r + 8*(c^s). 16 u64 = 32 regs.
    u64 E2[4][4];
#pragma unroll
    for (int s = 0; s < 4; ++s) {
        const float* tr = trans + (r + 8 * (c ^ s)) * T_ + 8 * c;
#pragma unroll
        for (int m = 0; m < 4; ++m)
            E2[s][m] = pack2(__expf(__ldg(tr + 2 * m)), __expf(__ldg(tr + 2 * m + 1)));
    }

    // Init fv (linear domain): v[START]=1, else 0 (both exact in bf16).
    sv[0][t] = f2bf((t == START_) ? 1.0f : 0.0f);

    const float* fb = feats + (size_t)b * L_ * T_ + t;
    const unsigned* tb = tagw + (size_t)b * L_ * TS;

    float F[2][4];   // feat prefetch [buf][step]
    unsigned P[2];   // 4 tags byte-packed per buf
    int sc = 0;      // log2 scale accumulator
    float ge = 0.f;  // gold emission partial (this lane's state)
    float vcur = 0.f;

#define PF(I, G)                                                               \
    do {                                                                       \
        const int gc_ = ((G) < 256) ? (G) : 255;                               \
        const float* q_ = fb + gc_ * 128;                                      \
        _Pragma("unroll") for (int s_ = 0; s_ < 4; ++s_)                       \
            F[I][s_] = __ldg(q_ + s_ * 32);                                    \
        if (TS == 1) {                                                         \
            uint4 w_ = __ldg((const uint4*)(tb + gc_ * 4));                    \
            P[I] = w_.x | (w_.y << 8) | (w_.z << 16) | (w_.w << 24);           \
        } else {                                                               \
            uint4 a_ = __ldg((const uint4*)(tb + gc_ * 8));                    \
            uint4 c_ = __ldg((const uint4*)(tb + gc_ * 8 + 4));                \
            P[I] = a_.x | (a_.z << 8) | (c_.x << 16) | (c_.z << 24);           \
        }                                                                      \
    } while (0)

#define STEP(I, S, CUR, NXT, RN)                                               \
    do {                                                                       \
        const float f_ = F[I][S];                                              \
        /* one LDS.128: this chunk's 8 prevs as 4 bf16x2 words */              \
        const uint4 wv_ = *(const uint4*)&sv[CUR][8 * c];                      \
        const u64 w0_ = bf2f2(wv_.x);                                          \
        const u64 w1_ = bf2f2(wv_.y);                                          \
        const u64 w2_ = bf2f2(wv_.z);                                          \
        const u64 w3_ = bf2f2(wv_.w);                                          \
        u64 a0_ = 0ULL, a1_ = 0ULL, a2_ = 0ULL, a3_ = 0ULL;                    \
        fma2(a0_, w0_, E2[0][0]); fma2(a1_, w0_, E2[1][0]);                    \
        fma2(a2_, w0_, E2[2][0]); fma2(a3_, w0_, E2[3][0]);                    \
        fma2(a0_, w1_, E2[0][1]); fma2(a1_, w1_, E2[1][1]);                    \
        fma2(a2_, w1_, E2[2][1]); fma2(a3_, w1_, E2[3][1]);                    \
        fma2(a0_, w2_, E2[0][2]); fma2(a1_, w2_, E2[1][2]);                    \
        fma2(a2_, w2_, E2[2][2]); fma2(a3_, w2_, E2[3][2]);                    \
        fma2(a0_, w3_, E2[0][3]); fma2(a1_, w3_, E2[1][3]);                    \
        fma2(a2_, w3_, E2[2][3]); fma2(a3_, w3_, E2[3][3]);                    \
        /* reduce-scatter: xor16 merges chunk c^2, xor8 merges c^1 (+c^3) */   \
        a0_ = add2(a0_, __shfl_xor_sync(FULL_, a2_, 16));                      \
        a1_ = add2(a1_, __shfl_xor_sync(FULL_, a3_, 16));                      \
        a0_ = add2(a0_, __shfl_xor_sync(FULL_, a1_, 8));                       \
        float lo_, hi_;                                                        \
        unpack2(a0_, lo_, hi_);                                                \
        float v_ = (lo_ + hi_) * __expf(f_);                                   \
        if (RN) {                                                              \
            unsigned m_ = __reduce_max_sync(FULL_, __float_as_uint(v_));       \
            int e_ = (int)(m_ >> 23) - 127;                                    \
            e_ = max(-64, min(e_, 120));                                       \
            v_ *= __uint_as_float((unsigned)(127 - e_) << 23);                 \
            sc += e_;                                                          \
        }                                                                      \
        vcur = v_;                                                             \
        sv[NXT][t] = f2bf(v_);                                                 \
        const unsigned gt_ = (P[I] >> (8 * (S))) & 0xffu;                      \
        ge += (t == (int)gt_) ? f_ : 0.0f;                                     \
        __syncthreads();                                                       \
    } while (0)

#define GROUP(I)                                                               \
    do {                                                                       \
        STEP(I, 0, 0, 1, false);                                               \
        STEP(I, 1, 1, 0, false);                                               \
        STEP(I, 2, 0, 1, false);                                               \
        STEP(I, 3, 1, 0, true);                                                \
    } while (0)

    // Prologue: fill both prefetch buffers; make init stores visible.
    PF(0, 0);
    PF(1, 1);
    __syncthreads();

    // 256 groups of 4 steps; refill each buffer right after consuming it.
#pragma unroll 1
    for (int g2 = 0; g2 < 128; ++g2) {
        GROUP(0);
        PF(0, 2 * g2 + 2);
        GROUP(1);
        PF(1, 2 * g2 + 3);
    }

#undef PF
#undef STEP
#undef GROUP

    // ---- bulk gold transition score: sum_l trans[g_l, g_{l-1}] (+STOP term).
    float gt = 0.f;
    {
        unsigned carry = START_;
#pragma unroll 4
        for (int it = 0; it < 32; ++it) {
            const int l = it * 32 + t;
            unsigned g = (TS == 1) ? __ldg(tb + l) : __ldg(tb + 2 * l);
            unsigned prev = __shfl_up_sync(FULL_, g, 1);
            if (t == 0) prev = carry;
            carry = __shfl_sync(FULL_, g, 31);
            gt += __ldg(trans + g * 32u + prev);
        }
        if (t == 0) gt += __ldg(trans + STOP_ * 32u + carry);
    }

    // ---- epilogue: alpha = log( sum_t v[t]*exp(trans[STOP,t]) ) + sc*ln2 ----
    float z = vcur * __expf(__ldg(trans + STOP_ * T_ + t));
    float gold = ge + gt;
#pragma unroll
    for (int o = 16; o > 0; o >>= 1) {
        z += __shfl_xor_sync(FULL_, z, o);
        gold += __shfl_xor_sync(FULL_, gold, o);
    }

    if (t == 0) {
        const float LN2 = 0.6931471805599453f;
        out[b] = __logf(z) + (float)sc * LN2 - gold;
    }
}

__global__ void __launch_bounds__(32, 28) crf_fwd(const float* __restrict__ feats,
                                                  const float* __restrict__ trans,
                                                  const unsigned* __restrict__ tagw,
                                                  float* __restrict__ out) {
    __shared__ __align__(16) unsigned short sv[2][32];  // bf16 fv, double-buffered
    // Tag dtype detection: int64 tags (values < 30) have all-zero odd words.
    unsigned oddw = __ldg(tagw + 2 * threadIdx.x + 1);
    if (__any_sync(FULL_, oddw != 0)) {
        crf_body<1>(feats, trans, tagw, out, sv);  // int32 tags
    } else {
        crf_body<2>(feats, trans, tagw, out, sv);  // int64 tags
    }
}

}  // namespace

extern "C" void kernel_launch(void* const* d_in, const int* in_sizes, int n_in,
                              void* d_out, int out_size) {
    const float* feats = (const float*)d_in[0];
    const float* trans = (const float*)d_in[1];
    const unsigned* tagw = (const unsigned*)d_in[2];
    float* out = (float*)d_out;

    const int B = in_sizes[2] / L_;  // element count = B*L for either tag dtype
    crf_fwd<<<B, 32>>>(feats, trans, tagw, out);
}